// round 1
// baseline (speedup 1.0000x reference)
#include <cuda_runtime.h>
#include <math_constants.h>

#define NSEQ 1024
#define DHEAD 64
#define HEADS 8
#define BM 64
#define BN 64
#define NTHREADS 128

// smem strides (floats)
#define QS_STRIDE 68   // float4-aligned, bank-spread
#define KS_STRIDE 65   // scalar loads, conflict-free
#define PS_STRIDE 65
#define VS_STRIDE 64   // float4 loads along d

#define SM_Q 0
#define SM_K (BM * QS_STRIDE)                 // 4352
#define SM_P (SM_K + BN * KS_STRIDE)          // 8512
#define SM_V (SM_P + BN * PS_STRIDE)          // 12672
#define SM_M (SM_V + BN * VS_STRIDE)          // 16768
#define SM_TOTAL (SM_M + BN)                  // 16832 floats = 67328 bytes

__global__ __launch_bounds__(NTHREADS, 3)
void attend_kernel(const float* __restrict__ q,
                   const float* __restrict__ k,
                   const float* __restrict__ v,
                   const unsigned int* __restrict__ mask,
                   const float* __restrict__ bias,
                   float* __restrict__ out)
{
    extern __shared__ float sm[];
    float* Qs = sm + SM_Q;
    float* Ks = sm + SM_K;
    float* Ps = sm + SM_P;   // stores P transposed: Ps[col][row]
    float* Vs = sm + SM_V;
    float* Ms = sm + SM_M;   // key-padding additive mask per column: 0 or -inf

    const int tid = threadIdx.x;
    const int ty  = tid >> 4;   // 0..7  -> rows ty*8 .. ty*8+7
    const int tx  = tid & 15;   // 0..15 -> cols tx*4 .. tx*4+3
    const int bm  = blockIdx.x; // query tile index
    const int bh  = blockIdx.y; // b*H + h
    const int b   = bh >> 3;
    const int i0  = bm * BM;

    const float scale = 0.125f;            // 1/sqrt(64)
    const float NEG   = -CUDART_INF_F;

    // ---- load Q tile into smem ----
    {
        const float* qbase = q + ((size_t)bh * NSEQ + i0) * DHEAD;
        #pragma unroll
        for (int t = 0; t < 8; t++) {
            int f   = tid + NTHREADS * t;   // 0..1023 (float4 units)
            int row = f >> 4;
            int kk  = (f & 15) << 2;
            float4 val = *(const float4*)(qbase + row * DHEAD + kk);
            *(float4*)(Qs + row * QS_STRIDE + kk) = val;
        }
    }

    float o[8][4];
    float mrow[8], lrow[8];
    #pragma unroll
    for (int r = 0; r < 8; r++) {
        mrow[r] = NEG;
        lrow[r] = 0.f;
        #pragma unroll
        for (int c = 0; c < 4; c++) o[r][c] = 0.f;
    }

    const float* bias_base = bias + ((size_t)bh * NSEQ + i0) * NSEQ;

    for (int bn = 0; bn <= bm; bn++) {
        const int j0 = bn * BN;

        __syncthreads();  // previous GEMM2 done reading Ps/Vs/Ks

        // ---- load K, V tiles + padding mask ----
        {
            const float* kb = k + ((size_t)b * NSEQ + j0) * DHEAD;
            const float* vb = v + ((size_t)b * NSEQ + j0) * DHEAD;
            #pragma unroll
            for (int t = 0; t < 8; t++) {
                int f   = tid + NTHREADS * t;
                int row = f >> 4;
                int kk  = (f & 15) << 2;
                float4 kv = *(const float4*)(kb + row * DHEAD + kk);
                Ks[row * KS_STRIDE + kk + 0] = kv.x;
                Ks[row * KS_STRIDE + kk + 1] = kv.y;
                Ks[row * KS_STRIDE + kk + 2] = kv.z;
                Ks[row * KS_STRIDE + kk + 3] = kv.w;
                float4 vv = *(const float4*)(vb + row * DHEAD + kk);
                *(float4*)(Vs + row * VS_STRIDE + kk) = vv;
            }
            if (tid < BN) {
                // works whether the bool mask was materialized as int32 or float32:
                // "false" is all-zero bits in both encodings.
                Ms[tid] = (mask[b * NSEQ + j0 + tid] != 0u) ? 0.f : NEG;
            }
        }
        __syncthreads();

        // ---- GEMM1: S = Q * K^T  (8x4 per thread) ----
        float s[8][4];
        #pragma unroll
        for (int r = 0; r < 8; r++)
            #pragma unroll
            for (int c = 0; c < 4; c++) s[r][c] = 0.f;

        #pragma unroll
        for (int kk = 0; kk < DHEAD; kk += 4) {
            float4 qv[8];
            #pragma unroll
            for (int r = 0; r < 8; r++)
                qv[r] = *(const float4*)(Qs + (ty * 8 + r) * QS_STRIDE + kk);
            #pragma unroll
            for (int c = 0; c < 4; c++) {
                const float* kr = Ks + (tx * 4 + c) * KS_STRIDE + kk;
                float k0 = kr[0], k1 = kr[1], k2 = kr[2], k3 = kr[3];
                #pragma unroll
                for (int r = 0; r < 8; r++) {
                    float acc = s[r][c];
                    acc = fmaf(qv[r].x, k0, acc);
                    acc = fmaf(qv[r].y, k1, acc);
                    acc = fmaf(qv[r].z, k2, acc);
                    acc = fmaf(qv[r].w, k3, acc);
                    s[r][c] = acc;
                }
            }
        }

        // ---- epilogue: bias + masks + online softmax, write P^T ----
        float mcol[4];
        #pragma unroll
        for (int c = 0; c < 4; c++) mcol[c] = Ms[tx * 4 + c];

        #pragma unroll
        for (int r = 0; r < 8; r++) {
            const int row = ty * 8 + r;
            const int gi  = i0 + row;
            const float* brow = bias_base + (size_t)row * NSEQ + j0;
            float sv[4];
            float mloc = NEG;
            #pragma unroll
            for (int c = 0; c < 4; c++) {
                const int col = tx * 4 + c;
                float x = fmaf(s[r][c], scale, brow[col]) + mcol[c];
                if (j0 + col > gi) x = NEG;   // causal
                sv[c] = x;
                mloc = fmaxf(mloc, x);
            }
            // row-max over the 16 threads sharing this row (same half-warp)
            mloc = fmaxf(mloc, __shfl_xor_sync(0xffffffffu, mloc, 8));
            mloc = fmaxf(mloc, __shfl_xor_sync(0xffffffffu, mloc, 4));
            mloc = fmaxf(mloc, __shfl_xor_sync(0xffffffffu, mloc, 2));
            mloc = fmaxf(mloc, __shfl_xor_sync(0xffffffffu, mloc, 1));

            float mnew = fmaxf(mrow[r], mloc);
            float corr = __expf(mrow[r] - mnew);   // exp(-inf - finite) = 0 on first tile
            mrow[r] = mnew;

            float lloc = 0.f;
            #pragma unroll
            for (int c = 0; c < 4; c++) {
                float p = __expf(sv[c] - mnew);    // masked: exp(-inf) = 0
                Ps[(tx * 4 + c) * PS_STRIDE + row] = p;
                lloc += p;
            }
            lloc += __shfl_xor_sync(0xffffffffu, lloc, 8);
            lloc += __shfl_xor_sync(0xffffffffu, lloc, 4);
            lloc += __shfl_xor_sync(0xffffffffu, lloc, 2);
            lloc += __shfl_xor_sync(0xffffffffu, lloc, 1);

            lrow[r] = lrow[r] * corr + lloc;
            #pragma unroll
            for (int c = 0; c < 4; c++) o[r][c] *= corr;
        }
        __syncthreads();  // P^T fully written before GEMM2

        // ---- GEMM2: O += P * V ----
        #pragma unroll 8
        for (int j = 0; j < BN; j++) {
            float4 vv = *(const float4*)(Vs + j * VS_STRIDE + tx * 4);
            const float* pcol = Ps + j * PS_STRIDE + ty * 8;
            #pragma unroll
            for (int r = 0; r < 8; r++) {
                float p = pcol[r];
                o[r][0] = fmaf(p, vv.x, o[r][0]);
                o[r][1] = fmaf(p, vv.y, o[r][1]);
                o[r][2] = fmaf(p, vv.z, o[r][2]);
                o[r][3] = fmaf(p, vv.w, o[r][3]);
            }
        }
    }

    // ---- finalize: O / l, write out ----
    float* ob = out + ((size_t)bh * NSEQ + i0) * DHEAD;
    #pragma unroll
    for (int r = 0; r < 8; r++) {
        float inv = 1.f / lrow[r];
        float4 res = make_float4(o[r][0] * inv, o[r][1] * inv,
                                 o[r][2] * inv, o[r][3] * inv);
        *(float4*)(ob + (ty * 8 + r) * DHEAD + tx * 4) = res;
    }
}

extern "C" void kernel_launch(void* const* d_in, const int* in_sizes, int n_in,
                              void* d_out, int out_size)
{
    const float*        q    = (const float*)d_in[0];
    const float*        k    = (const float*)d_in[1];
    const float*        v    = (const float*)d_in[2];
    const unsigned int* mask = (const unsigned int*)d_in[3];
    const float*        bias = (const float*)d_in[4];
    float*              out  = (float*)d_out;

    // >48KB dynamic smem requires the attribute; idempotent + capture-safe.
    cudaFuncSetAttribute(attend_kernel,
                         cudaFuncAttributeMaxDynamicSharedMemorySize,
                         SM_TOTAL * (int)sizeof(float));

    dim3 grid(NSEQ / BM, 4 * HEADS);   // 16 x 32
    attend_kernel<<<grid, NTHREADS, SM_TOTAL * sizeof(float)>>>(
        q, k, v, mask, bias, out);
}

// round 2
// speedup vs baseline: 2.2585x; 2.2585x over previous
#include <cuda_runtime.h>
#include <math_constants.h>

#define NSEQ 1024
#define DHEAD 64
#define HEADS 8
#define BM 64
#define BN 64
#define NTHREADS 128
#define NWARPS 4

// smem strides (32-bit words), chosen for conflict-free fragment loads
#define KS_STRIDE 68   // GEMM1 B-frag: (4g+tg) mod 32 -> 32 distinct banks
#define VS_STRIDE 72   // GEMM2 B-frag: (8tg+g+8nt) mod 32 -> 32 distinct banks
#define PS_STRIDE 68   // GEMM2 A-frag: (4g+tg) mod 32 -> 32 distinct banks

#define SM_K 0
#define SM_V (SM_K + BN * KS_STRIDE)            // 4352
#define SM_P (SM_V + BN * VS_STRIDE)            // 8960
#define SM_M (SM_P + BM * PS_STRIDE)            // 13312
#define SM_TOTAL (SM_M + BN)                    // 13376 words = 53504 B

__device__ __forceinline__ unsigned f2tf32(float x) {
    unsigned r;
    asm("cvt.rna.tf32.f32 %0, %1;" : "=r"(r) : "f"(x));
    return r;
}

__device__ __forceinline__ void mma_tf32(float (&c)[4], const unsigned (&a)[4],
                                         unsigned b0, unsigned b1) {
    asm volatile(
        "mma.sync.aligned.m16n8k8.row.col.f32.tf32.tf32.f32 "
        "{%0,%1,%2,%3}, {%4,%5,%6,%7}, {%8,%9}, {%0,%1,%2,%3};"
        : "+f"(c[0]), "+f"(c[1]), "+f"(c[2]), "+f"(c[3])
        : "r"(a[0]), "r"(a[1]), "r"(a[2]), "r"(a[3]), "r"(b0), "r"(b1));
}

__global__ __launch_bounds__(NTHREADS)
void attend_kernel(const float* __restrict__ q,
                   const float* __restrict__ k,
                   const float* __restrict__ v,
                   const unsigned int* __restrict__ mask,
                   const float* __restrict__ bias,
                   float* __restrict__ out)
{
    extern __shared__ unsigned smu[];
    unsigned* KsU = smu + SM_K;
    unsigned* VsU = smu + SM_V;
    unsigned* PsU = smu + SM_P;
    float*    Msf = (float*)(smu + SM_M);

    const int tid  = threadIdx.x;
    const int warp = tid >> 5;
    const int lane = tid & 31;
    const int g    = lane >> 2;   // 0..7
    const int tg   = lane & 3;    // 0..3
    const int bm   = blockIdx.x;
    const int bh   = blockIdx.y;  // b*H + h
    const int b    = bh >> 3;
    const int i0   = bm * BM;

    const int r0 = warp * 16 + g;   // tile-local row (first)
    const int r1 = r0 + 8;          // tile-local row (second)

    const float scale = 0.125f;     // 1/sqrt(64)
    const float NEG   = -CUDART_INF_F;

    // ---- stage Q tile (tf32) into Ps buffer, pull fragments into registers ----
    {
        const float* qbase = q + ((size_t)bh * NSEQ + i0) * DHEAD;
        #pragma unroll
        for (int t = 0; t < 8; t++) {
            int f   = tid + NTHREADS * t;    // float4 units, 0..1023
            int row = f >> 4;
            int c   = (f & 15) << 2;
            float4 val = *(const float4*)(qbase + row * DHEAD + c);
            unsigned* dst = PsU + row * PS_STRIDE + c;
            dst[0] = f2tf32(val.x); dst[1] = f2tf32(val.y);
            dst[2] = f2tf32(val.z); dst[3] = f2tf32(val.w);
        }
    }
    __syncthreads();
    unsigned qf[8][4];
    #pragma unroll
    for (int kk = 0; kk < 8; kk++) {
        qf[kk][0] = PsU[r0 * PS_STRIDE + kk * 8 + tg];
        qf[kk][1] = PsU[r1 * PS_STRIDE + kk * 8 + tg];
        qf[kk][2] = PsU[r0 * PS_STRIDE + kk * 8 + tg + 4];
        qf[kk][3] = PsU[r1 * PS_STRIDE + kk * 8 + tg + 4];
    }

    float o[8][4];
    #pragma unroll
    for (int nt = 0; nt < 8; nt++)
        #pragma unroll
        for (int c = 0; c < 4; c++) o[nt][c] = 0.f;
    float m0 = NEG, m1 = NEG, l0 = 0.f, l1 = 0.f;

    const float* bias0 = bias + ((size_t)bh * NSEQ + (i0 + r0)) * NSEQ;
    const float* bias1 = bias + ((size_t)bh * NSEQ + (i0 + r1)) * NSEQ;

    for (int bn = 0; bn <= bm; bn++) {
        const int j0 = bn * BN;

        __syncthreads();  // all warps done reading Ks/Vs (and Q stage on iter 0)

        // ---- fill K/V tiles as tf32 bits + padding mask ----
        {
            const float* kb = k + ((size_t)b * NSEQ + j0) * DHEAD;
            const float* vb = v + ((size_t)b * NSEQ + j0) * DHEAD;
            #pragma unroll
            for (int t = 0; t < 8; t++) {
                int f   = tid + NTHREADS * t;
                int row = f >> 4;
                int c   = (f & 15) << 2;
                float4 kv = *(const float4*)(kb + row * DHEAD + c);
                unsigned* kd = KsU + row * KS_STRIDE + c;
                kd[0] = f2tf32(kv.x); kd[1] = f2tf32(kv.y);
                kd[2] = f2tf32(kv.z); kd[3] = f2tf32(kv.w);
                float4 vv = *(const float4*)(vb + row * DHEAD + c);
                unsigned* vd = VsU + row * VS_STRIDE + c;
                vd[0] = f2tf32(vv.x); vd[1] = f2tf32(vv.y);
                vd[2] = f2tf32(vv.z); vd[3] = f2tf32(vv.w);
            }
            if (tid < BN)
                Msf[tid] = (mask[b * NSEQ + j0 + tid] != 0u) ? 0.f : NEG;
        }
        __syncthreads();

        // ---- GEMM1: S = Q * K^T via tf32 mma ----
        float s[8][4];
        #pragma unroll
        for (int nt = 0; nt < 8; nt++)
            #pragma unroll
            for (int c = 0; c < 4; c++) s[nt][c] = 0.f;

        #pragma unroll
        for (int kk = 0; kk < 8; kk++) {
            #pragma unroll
            for (int nt = 0; nt < 8; nt++) {
                unsigned b0 = KsU[(nt * 8 + g) * KS_STRIDE + kk * 8 + tg];
                unsigned b1 = KsU[(nt * 8 + g) * KS_STRIDE + kk * 8 + tg + 4];
                mma_tf32(s[nt], qf[kk], b0, b1);
            }
        }

        // ---- epilogue: bias + masks + online softmax; write P (tf32) ----
        const bool diag = (bn == bm);
        float vmax0 = NEG, vmax1 = NEG;
        #pragma unroll
        for (int nt = 0; nt < 8; nt++) {
            const int c0 = nt * 8 + 2 * tg;
            float2 bv0 = *(const float2*)(bias0 + j0 + c0);
            float2 bv1 = *(const float2*)(bias1 + j0 + c0);
            float2 mk  = *(const float2*)(Msf + c0);
            float x00 = fmaf(s[nt][0], scale, bv0.x) + mk.x;
            float x01 = fmaf(s[nt][1], scale, bv0.y) + mk.y;
            float x10 = fmaf(s[nt][2], scale, bv1.x) + mk.x;
            float x11 = fmaf(s[nt][3], scale, bv1.y) + mk.y;
            if (diag) {
                if (c0     > r0) x00 = NEG;
                if (c0 + 1 > r0) x01 = NEG;
                if (c0     > r1) x10 = NEG;
                if (c0 + 1 > r1) x11 = NEG;
            }
            s[nt][0] = x00; s[nt][1] = x01; s[nt][2] = x10; s[nt][3] = x11;
            vmax0 = fmaxf(vmax0, fmaxf(x00, x01));
            vmax1 = fmaxf(vmax1, fmaxf(x10, x11));
        }
        vmax0 = fmaxf(vmax0, __shfl_xor_sync(0xffffffffu, vmax0, 1));
        vmax0 = fmaxf(vmax0, __shfl_xor_sync(0xffffffffu, vmax0, 2));
        vmax1 = fmaxf(vmax1, __shfl_xor_sync(0xffffffffu, vmax1, 1));
        vmax1 = fmaxf(vmax1, __shfl_xor_sync(0xffffffffu, vmax1, 2));

        float mn0 = fmaxf(m0, vmax0);
        float mn1 = fmaxf(m1, vmax1);
        float corr0 = __expf(m0 - mn0);   // exp(-inf) = 0 on first tile
        float corr1 = __expf(m1 - mn1);
        m0 = mn0; m1 = mn1;

        float sum0 = 0.f, sum1 = 0.f;
        #pragma unroll
        for (int nt = 0; nt < 8; nt++) {
            const int c0 = nt * 8 + 2 * tg;
            float p00 = __expf(s[nt][0] - m0);
            float p01 = __expf(s[nt][1] - m0);
            float p10 = __expf(s[nt][2] - m1);
            float p11 = __expf(s[nt][3] - m1);
            sum0 += p00 + p01;
            sum1 += p10 + p11;
            uint2 w0 = make_uint2(f2tf32(p00), f2tf32(p01));
            uint2 w1 = make_uint2(f2tf32(p10), f2tf32(p11));
            *(uint2*)(PsU + r0 * PS_STRIDE + c0) = w0;
            *(uint2*)(PsU + r1 * PS_STRIDE + c0) = w1;
        }
        sum0 += __shfl_xor_sync(0xffffffffu, sum0, 1);
        sum0 += __shfl_xor_sync(0xffffffffu, sum0, 2);
        sum1 += __shfl_xor_sync(0xffffffffu, sum1, 1);
        sum1 += __shfl_xor_sync(0xffffffffu, sum1, 2);
        l0 = l0 * corr0 + sum0;
        l1 = l1 * corr1 + sum1;

        #pragma unroll
        for (int nt = 0; nt < 8; nt++) {
            o[nt][0] *= corr0; o[nt][1] *= corr0;
            o[nt][2] *= corr1; o[nt][3] *= corr1;
        }
        __syncwarp();  // P region is per-warp private: warp-level sync suffices

        // ---- GEMM2: O += P * V via tf32 mma ----
        #pragma unroll
        for (int kk = 0; kk < 8; kk++) {
            unsigned pa[4];
            pa[0] = PsU[r0 * PS_STRIDE + kk * 8 + tg];
            pa[1] = PsU[r1 * PS_STRIDE + kk * 8 + tg];
            pa[2] = PsU[r0 * PS_STRIDE + kk * 8 + tg + 4];
            pa[3] = PsU[r1 * PS_STRIDE + kk * 8 + tg + 4];
            #pragma unroll
            for (int nt = 0; nt < 8; nt++) {
                unsigned b0 = VsU[(kk * 8 + tg) * VS_STRIDE + nt * 8 + g];
                unsigned b1 = VsU[(kk * 8 + tg + 4) * VS_STRIDE + nt * 8 + g];
                mma_tf32(o[nt], pa, b0, b1);
            }
        }
    }

    // ---- finalize: O / l, write out ----
    float inv0 = 1.f / l0;
    float inv1 = 1.f / l1;
    float* ob = out + ((size_t)bh * NSEQ + i0) * DHEAD;
    #pragma unroll
    for (int nt = 0; nt < 8; nt++) {
        const int c0 = nt * 8 + 2 * tg;
        float2 w0 = make_float2(o[nt][0] * inv0, o[nt][1] * inv0);
        float2 w1 = make_float2(o[nt][2] * inv1, o[nt][3] * inv1);
        *(float2*)(ob + r0 * DHEAD + c0) = w0;
        *(float2*)(ob + r1 * DHEAD + c0) = w1;
    }
}

extern "C" void kernel_launch(void* const* d_in, const int* in_sizes, int n_in,
                              void* d_out, int out_size)
{
    const float*        q    = (const float*)d_in[0];
    const float*        k    = (const float*)d_in[1];
    const float*        v    = (const float*)d_in[2];
    const unsigned int* mask = (const unsigned int*)d_in[3];
    const float*        bias = (const float*)d_in[4];
    float*              out  = (float*)d_out;

    cudaFuncSetAttribute(attend_kernel,
                         cudaFuncAttributeMaxDynamicSharedMemorySize,
                         SM_TOTAL * (int)sizeof(unsigned));

    dim3 grid(NSEQ / BM, 4 * HEADS);   // 16 x 32
    attend_kernel<<<grid, NTHREADS, SM_TOTAL * sizeof(unsigned)>>>(
        q, k, v, mask, bias, out);
}

// round 3
// speedup vs baseline: 3.5012x; 1.5502x over previous
#include <cuda_runtime.h>
#include <cuda_fp16.h>
#include <math_constants.h>

#define NSEQ 1024
#define DHEAD 64
#define HEADS 8
#define BM 64
#define BN 64
#define NTHREADS 128

// shared memory word (4B) offsets
#define SW_KRAW 0                         // float [64][64]
#define SW_VRAW (SW_KRAW + 64*64)         // float [64][64]
#define SW_KS   (SW_VRAW + 64*64)         // half  [64][64] swizzled (2048 words)
#define SW_VS   (SW_KS + 2048)            // half  [64][64] swizzled
#define SW_BIAS (SW_VS + 2048)            // float [2][64][72]
#define BIAS_STRIDE 72
#define BIAS_BUF (64*BIAS_STRIDE)
#define SW_MASK (SW_BIAS + 2*BIAS_BUF)    // float [1024]
#define SW_TOTAL (SW_MASK + NSEQ)         // 22528 words = 90112 B

__device__ __forceinline__ unsigned packh2(float lo, float hi) {
    __half2 h = __floats2half2_rn(lo, hi);
    return *(unsigned*)&h;
}

__device__ __forceinline__ void ldsm_x4(unsigned& r0, unsigned& r1,
                                        unsigned& r2, unsigned& r3, unsigned addr) {
    asm volatile("ldmatrix.sync.aligned.m8n8.x4.shared.b16 {%0,%1,%2,%3}, [%4];"
                 : "=r"(r0), "=r"(r1), "=r"(r2), "=r"(r3) : "r"(addr));
}
__device__ __forceinline__ void ldsm_x4_t(unsigned& r0, unsigned& r1,
                                          unsigned& r2, unsigned& r3, unsigned addr) {
    asm volatile("ldmatrix.sync.aligned.m8n8.x4.trans.shared.b16 {%0,%1,%2,%3}, [%4];"
                 : "=r"(r0), "=r"(r1), "=r"(r2), "=r"(r3) : "r"(addr));
}
__device__ __forceinline__ void mma_f16(float (&c)[4], const unsigned (&a)[4],
                                        unsigned b0, unsigned b1) {
    asm volatile(
        "mma.sync.aligned.m16n8k16.row.col.f32.f16.f16.f32 "
        "{%0,%1,%2,%3}, {%4,%5,%6,%7}, {%8,%9}, {%0,%1,%2,%3};"
        : "+f"(c[0]), "+f"(c[1]), "+f"(c[2]), "+f"(c[3])
        : "r"(a[0]), "r"(a[1]), "r"(a[2]), "r"(a[3]), "r"(b0), "r"(b1));
}
__device__ __forceinline__ void cp16(unsigned dst_sh, const void* src) {
    asm volatile("cp.async.cg.shared.global [%0], [%1], 16;" :: "r"(dst_sh), "l"(src));
}

__global__ __launch_bounds__(NTHREADS, 2)
void attend_kernel(const float* __restrict__ q,
                   const float* __restrict__ k,
                   const float* __restrict__ v,
                   const unsigned int* __restrict__ mask,
                   const float* __restrict__ bias,
                   float* __restrict__ out)
{
    extern __shared__ float sm[];
    const unsigned sh_base = (unsigned)__cvta_generic_to_shared(sm);

    const int tid  = threadIdx.x;
    const int lane = tid & 31;
    const int warp = tid >> 5;
    const int g    = lane >> 2;
    const int tg   = lane & 3;
    const int bm   = (gridDim.x - 1) - blockIdx.x;  // reversed: heavy tiles first
    const int bh   = blockIdx.y;                    // b*H + h
    const int b    = bh >> 3;
    const int i0   = bm * BM;
    const int r0   = warp * 16 + g;
    const int r1   = r0 + 8;

    const float scale = 0.125f;
    const float NEG   = -CUDART_INF_F;

    const float* kbB  = k + (size_t)b * NSEQ * DHEAD;
    const float* vbB  = v + (size_t)b * NSEQ * DHEAD;
    const float* bTil = bias + ((size_t)bh * NSEQ + i0) * NSEQ;

    const int frow = tid >> 4;        // loader row (0..7 base, step 8)
    const int fc   = tid & 15;        // loader chunk

    // ---- prologue: async-load tile 0 (K,V raw + bias buf0) ----
    {
        const float* kb = kbB;                 // j0 = 0
        const float* vb = vbB;
        #pragma unroll
        for (int t = 0; t < 8; t++) {
            int row = frow + t * 8;
            cp16(sh_base + (SW_KRAW + row * 64 + fc * 4) * 4, kb + row * DHEAD + fc * 4);
            cp16(sh_base + (SW_VRAW + row * 64 + fc * 4) * 4, vb + row * DHEAD + fc * 4);
            cp16(sh_base + (SW_BIAS + row * BIAS_STRIDE + fc * 4) * 4,
                 bTil + (size_t)row * NSEQ + fc * 4);
        }
        asm volatile("cp.async.commit_group;");
    }

    // ---- key-padding mask -> smem (whole row, once) ----
    {
        float* Ms = sm + SW_MASK;
        const unsigned int* mrow = mask + b * NSEQ;
        #pragma unroll
        for (int t = 0; t < 8; t++)
            Ms[tid + t * NTHREADS] = (mrow[tid + t * NTHREADS] != 0u) ? 0.f : NEG;
    }

    // ---- Q fragments (held in registers for whole CTA) ----
    unsigned qf[4][4];
    {
        const float* q0 = q + ((size_t)bh * NSEQ + i0 + r0) * DHEAD;
        const float* q1 = q0 + 8 * DHEAD;
        #pragma unroll
        for (int kk = 0; kk < 4; kk++) {
            float2 x0 = *(const float2*)(q0 + 16 * kk + 2 * tg);
            float2 x1 = *(const float2*)(q1 + 16 * kk + 2 * tg);
            float2 x2 = *(const float2*)(q0 + 16 * kk + 2 * tg + 8);
            float2 x3 = *(const float2*)(q1 + 16 * kk + 2 * tg + 8);
            qf[kk][0] = packh2(x0.x, x0.y);
            qf[kk][1] = packh2(x1.x, x1.y);
            qf[kk][2] = packh2(x2.x, x2.y);
            qf[kk][3] = packh2(x3.x, x3.y);
        }
    }

    float o[8][4];
    #pragma unroll
    for (int nt = 0; nt < 8; nt++)
        #pragma unroll
        for (int c = 0; c < 4; c++) o[nt][c] = 0.f;
    float m0 = NEG, m1 = NEG, l0 = 0.f, l1 = 0.f;

    // static parts of ldmatrix addressing
    const int lrA = (lane & 7) + ((lane >> 4) << 3);       // GEMM1 row-within
    const int lcA = (lane >> 3) & 1;                       // GEMM1 chunk bit
    const int lrB = (lane & 7) + (((lane >> 3) & 1) << 3); // GEMM2 row-within
    const int lcB = (lane >> 4) & 1;                       // GEMM2 chunk bit
    const unsigned ksB = sh_base + SW_KS * 4;
    const unsigned vsB = sh_base + SW_VS * 4;

    for (int bn = 0; bn <= bm; bn++) {
        const int j0 = bn * BN;

        asm volatile("cp.async.wait_group 0;");
        __syncthreads();   // raw ready; previous tile's GEMMs done with Ks/Vs

        // ---- convert raw fp32 -> swizzled fp16 smem ----
        {
            const float* Kr = sm + SW_KRAW;
            const float* Vr = sm + SW_VRAW;
            char* smc = (char*)sm;
            const int chunk16 = fc >> 1;
            const int sub8    = (fc & 1) << 3;
            #pragma unroll
            for (int t = 0; t < 8; t++) {
                int row = frow + t * 8;
                int dsw = row * 128 + (((chunk16 ^ (row & 7)) << 4) | sub8);
                float4 kv = *(const float4*)(Kr + row * 64 + fc * 4);
                *(uint2*)(smc + SW_KS * 4 + dsw) =
                    make_uint2(packh2(kv.x, kv.y), packh2(kv.z, kv.w));
                float4 vv = *(const float4*)(Vr + row * 64 + fc * 4);
                *(uint2*)(smc + SW_VS * 4 + dsw) =
                    make_uint2(packh2(vv.x, vv.y), packh2(vv.z, vv.w));
            }
        }
        __syncthreads();   // Ks/Vs ready; raw free for next prefetch

        // ---- prefetch next tile (K,V raw + bias other buf) ----
        if (bn < bm) {
            const int jn = j0 + BN;
            const float* kb = kbB + (size_t)jn * DHEAD;
            const float* vb = vbB + (size_t)jn * DHEAD;
            const float* bt = bTil + jn;
            const int bufo = SW_BIAS + ((bn + 1) & 1) * BIAS_BUF;
            #pragma unroll
            for (int t = 0; t < 8; t++) {
                int row = frow + t * 8;
                cp16(sh_base + (SW_KRAW + row * 64 + fc * 4) * 4, kb + row * DHEAD + fc * 4);
                cp16(sh_base + (SW_VRAW + row * 64 + fc * 4) * 4, vb + row * DHEAD + fc * 4);
                cp16(sh_base + (bufo + row * BIAS_STRIDE + fc * 4) * 4,
                     bt + (size_t)row * NSEQ + fc * 4);
            }
            asm volatile("cp.async.commit_group;");
        }

        // ---- GEMM1: S = Q * K^T ----
        float s[8][4];
        #pragma unroll
        for (int nt = 0; nt < 8; nt++)
            #pragma unroll
            for (int c = 0; c < 4; c++) s[nt][c] = 0.f;

        #pragma unroll
        for (int kk = 0; kk < 4; kk++) {
            #pragma unroll
            for (int ntp = 0; ntp < 4; ntp++) {
                int row   = 16 * ntp + lrA;
                int chunk = 2 * kk + lcA;
                unsigned addr = ksB + row * 128 + ((chunk ^ (row & 7)) << 4);
                unsigned kb0, kb1, kb2, kb3;
                ldsm_x4(kb0, kb1, kb2, kb3, addr);
                mma_f16(s[2 * ntp],     qf[kk], kb0, kb1);
                mma_f16(s[2 * ntp + 1], qf[kk], kb2, kb3);
            }
        }

        // ---- epilogue: bias + masks + online softmax (P stays in regs) ----
        const bool diag = (bn == bm);
        const float* bb = sm + SW_BIAS + (bn & 1) * BIAS_BUF;
        const float* Ms = sm + SW_MASK + j0;
        float vmax0 = NEG, vmax1 = NEG;
        #pragma unroll
        for (int nt = 0; nt < 8; nt++) {
            const int c0 = nt * 8 + 2 * tg;
            float2 bv0 = *(const float2*)(bb + r0 * BIAS_STRIDE + c0);
            float2 bv1 = *(const float2*)(bb + r1 * BIAS_STRIDE + c0);
            float2 mk  = *(const float2*)(Ms + c0);
            float x00 = fmaf(s[nt][0], scale, bv0.x) + mk.x;
            float x01 = fmaf(s[nt][1], scale, bv0.y) + mk.y;
            float x10 = fmaf(s[nt][2], scale, bv1.x) + mk.x;
            float x11 = fmaf(s[nt][3], scale, bv1.y) + mk.y;
            if (diag) {
                if (c0     > r0) x00 = NEG;
                if (c0 + 1 > r0) x01 = NEG;
                if (c0     > r1) x10 = NEG;
                if (c0 + 1 > r1) x11 = NEG;
            }
            s[nt][0] = x00; s[nt][1] = x01; s[nt][2] = x10; s[nt][3] = x11;
            vmax0 = fmaxf(vmax0, fmaxf(x00, x01));
            vmax1 = fmaxf(vmax1, fmaxf(x10, x11));
        }
        vmax0 = fmaxf(vmax0, __shfl_xor_sync(0xffffffffu, vmax0, 1));
        vmax0 = fmaxf(vmax0, __shfl_xor_sync(0xffffffffu, vmax0, 2));
        vmax1 = fmaxf(vmax1, __shfl_xor_sync(0xffffffffu, vmax1, 1));
        vmax1 = fmaxf(vmax1, __shfl_xor_sync(0xffffffffu, vmax1, 2));

        float mn0 = fmaxf(m0, vmax0), mn1 = fmaxf(m1, vmax1);
        float corr0 = __expf(m0 - mn0), corr1 = __expf(m1 - mn1);
        m0 = mn0; m1 = mn1;

        unsigned ph0[8], ph1[8];
        float sum0 = 0.f, sum1 = 0.f;
        #pragma unroll
        for (int nt = 0; nt < 8; nt++) {
            float p00 = __expf(s[nt][0] - m0);
            float p01 = __expf(s[nt][1] - m0);
            float p10 = __expf(s[nt][2] - m1);
            float p11 = __expf(s[nt][3] - m1);
            sum0 += p00 + p01;
            sum1 += p10 + p11;
            ph0[nt] = packh2(p00, p01);
            ph1[nt] = packh2(p10, p11);
        }
        sum0 += __shfl_xor_sync(0xffffffffu, sum0, 1);
        sum0 += __shfl_xor_sync(0xffffffffu, sum0, 2);
        sum1 += __shfl_xor_sync(0xffffffffu, sum1, 1);
        sum1 += __shfl_xor_sync(0xffffffffu, sum1, 2);
        l0 = l0 * corr0 + sum0;
        l1 = l1 * corr1 + sum1;
        #pragma unroll
        for (int nt = 0; nt < 8; nt++) {
            o[nt][0] *= corr0; o[nt][1] *= corr0;
            o[nt][2] *= corr1; o[nt][3] *= corr1;
        }

        // ---- GEMM2: O += P * V  (A-frags direct from registers) ----
        #pragma unroll
        for (int kk = 0; kk < 4; kk++) {
            unsigned pa[4] = { ph0[2 * kk], ph1[2 * kk],
                               ph0[2 * kk + 1], ph1[2 * kk + 1] };
            #pragma unroll
            for (int ntp = 0; ntp < 4; ntp++) {
                int row   = 16 * kk + lrB;
                int chunk = 2 * ntp + lcB;
                unsigned addr = vsB + row * 128 + ((chunk ^ (row & 7)) << 4);
                unsigned v0, v1, v2, v3;
                ldsm_x4_t(v0, v1, v2, v3, addr);
                mma_f16(o[2 * ntp],     pa, v0, v1);
                mma_f16(o[2 * ntp + 1], pa, v2, v3);
            }
        }
    }

    // ---- finalize ----
    float inv0 = 1.f / l0, inv1 = 1.f / l1;
    float* ob = out + ((size_t)bh * NSEQ + i0) * DHEAD;
    #pragma unroll
    for (int nt = 0; nt < 8; nt++) {
        const int c0 = nt * 8 + 2 * tg;
        *(float2*)(ob + r0 * DHEAD + c0) =
            make_float2(o[nt][0] * inv0, o[nt][1] * inv0);
        *(float2*)(ob + r1 * DHEAD + c0) =
            make_float2(o[nt][2] * inv1, o[nt][3] * inv1);
    }
}

extern "C" void kernel_launch(void* const* d_in, const int* in_sizes, int n_in,
                              void* d_out, int out_size)
{
    const float*        q    = (const float*)d_in[0];
    const float*        k    = (const float*)d_in[1];
    const float*        v    = (const float*)d_in[2];
    const unsigned int* mask = (const unsigned int*)d_in[3];
    const float*        bias = (const float*)d_in[4];
    float*              out  = (float*)d_out;

    cudaFuncSetAttribute(attend_kernel,
                         cudaFuncAttributeMaxDynamicSharedMemorySize,
                         SW_TOTAL * (int)sizeof(float));

    dim3 grid(NSEQ / BM, 4 * HEADS);   // 16 x 32
    attend_kernel<<<grid, NTHREADS, SW_TOTAL * sizeof(float)>>>(
        q, k, v, mask, bias, out);
}

// round 4
// speedup vs baseline: 4.7952x; 1.3696x over previous
#include <cuda_runtime.h>
#include <cuda_fp16.h>
#include <math_constants.h>

#define NSEQ 1024
#define DHEAD 64
#define HEADS 8
#define BATCH 4
#define BM 64
#define BN 64
#define NTHREADS 128

// shared memory word (4B) offsets
#define SW_KS 0                          // half [2][64][64], swizzled (2*2048 words)
#define SW_VS 4096                       // half [2][64][64], swizzled
#define SW_BIAS 8192                     // float [2][64][72]
#define BIAS_STRIDE 72
#define BIAS_BUF (64*BIAS_STRIDE)
#define SW_MASK (SW_BIAS + 2*BIAS_BUF)   // float [1024]
#define SW_TOTAL (SW_MASK + NSEQ)        // 18432 words = 73728 B

// K/V converted to fp16 once per launch (allocation-free scratch)
__device__ __half2 g_kh[BATCH * NSEQ * DHEAD / 2];
__device__ __half2 g_vh[BATCH * NSEQ * DHEAD / 2];

__global__ void convert_kv_kernel(const float* __restrict__ k,
                                  const float* __restrict__ v)
{
    int i = blockIdx.x * blockDim.x + threadIdx.x;   // over half2 elements
    float2 a = ((const float2*)k)[i];
    g_kh[i] = __floats2half2_rn(a.x, a.y);
    float2 b = ((const float2*)v)[i];
    g_vh[i] = __floats2half2_rn(b.x, b.y);
}

__device__ __forceinline__ unsigned packh2(float lo, float hi) {
    __half2 h = __floats2half2_rn(lo, hi);
    return *(unsigned*)&h;
}
__device__ __forceinline__ void ldsm_x4(unsigned& r0, unsigned& r1,
                                        unsigned& r2, unsigned& r3, unsigned addr) {
    asm volatile("ldmatrix.sync.aligned.m8n8.x4.shared.b16 {%0,%1,%2,%3}, [%4];"
                 : "=r"(r0), "=r"(r1), "=r"(r2), "=r"(r3) : "r"(addr));
}
__device__ __forceinline__ void ldsm_x4_t(unsigned& r0, unsigned& r1,
                                          unsigned& r2, unsigned& r3, unsigned addr) {
    asm volatile("ldmatrix.sync.aligned.m8n8.x4.trans.shared.b16 {%0,%1,%2,%3}, [%4];"
                 : "=r"(r0), "=r"(r1), "=r"(r2), "=r"(r3) : "r"(addr));
}
__device__ __forceinline__ void mma_f16(float (&c)[4], const unsigned (&a)[4],
                                        unsigned b0, unsigned b1) {
    asm volatile(
        "mma.sync.aligned.m16n8k16.row.col.f32.f16.f16.f32 "
        "{%0,%1,%2,%3}, {%4,%5,%6,%7}, {%8,%9}, {%0,%1,%2,%3};"
        : "+f"(c[0]), "+f"(c[1]), "+f"(c[2]), "+f"(c[3])
        : "r"(a[0]), "r"(a[1]), "r"(a[2]), "r"(a[3]), "r"(b0), "r"(b1));
}
__device__ __forceinline__ void cp16(unsigned dst_sh, const void* src) {
    asm volatile("cp.async.cg.shared.global [%0], [%1], 16;" :: "r"(dst_sh), "l"(src));
}

__global__ __launch_bounds__(NTHREADS, 3)
void attend_kernel(const float* __restrict__ q,
                   const unsigned int* __restrict__ mask,
                   const float* __restrict__ bias,
                   float* __restrict__ out)
{
    extern __shared__ float sm[];
    const unsigned sh_base = (unsigned)__cvta_generic_to_shared(sm);

    const int tid  = threadIdx.x;
    const int lane = tid & 31;
    const int warp = tid >> 5;
    const int g    = lane >> 2;
    const int tg   = lane & 3;
    const int bm   = (gridDim.x - 1) - blockIdx.x;  // heavy tiles first
    const int bh   = blockIdx.y;                    // b*H + h
    const int b    = bh >> 3;
    const int i0   = bm * BM;
    const int r0   = warp * 16 + g;
    const int r1   = r0 + 8;

    const float scale = 0.125f;
    const float NEG   = -CUDART_INF_F;

    const char*  khB  = (const char*)g_kh + (size_t)b * NSEQ * DHEAD * 2;
    const char*  vhB  = (const char*)g_vh + (size_t)b * NSEQ * DHEAD * 2;
    const float* bTil = bias + ((size_t)bh * NSEQ + i0) * NSEQ;

    // loader decomposition
    const int kvRow = tid >> 3;        // K/V: 512 tasks, 4/thread (row step 16)
    const int kvCh  = tid & 7;
    const int bRow  = tid >> 4;        // bias: 1024 tasks, 8/thread (row step 8)
    const int bCh   = tid & 15;

    // ---- prologue: async-load tile 0 into buf 0 ----
    {
        #pragma unroll
        for (int t = 0; t < 4; t++) {
            int row = kvRow + t * 16;
            unsigned dsw = row * 128 + (((kvCh ^ (row & 7)) << 4));
            cp16(sh_base + SW_KS * 4 + dsw, khB + row * 128 + kvCh * 16);
            cp16(sh_base + SW_VS * 4 + dsw, vhB + row * 128 + kvCh * 16);
        }
        #pragma unroll
        for (int t = 0; t < 8; t++) {
            int row = bRow + t * 8;
            cp16(sh_base + (SW_BIAS + row * BIAS_STRIDE + bCh * 4) * 4,
                 bTil + (size_t)row * NSEQ + bCh * 4);
        }
        asm volatile("cp.async.commit_group;");
    }

    // ---- key-padding mask -> smem (whole row, once) ----
    {
        float* Ms = sm + SW_MASK;
        const unsigned int* mrow = mask + b * NSEQ;
        #pragma unroll
        for (int t = 0; t < 8; t++)
            Ms[tid + t * NTHREADS] = (mrow[tid + t * NTHREADS] != 0u) ? 0.f : NEG;
    }

    // ---- Q fragments (registers, whole CTA lifetime) ----
    unsigned qf[4][4];
    {
        const float* q0 = q + ((size_t)bh * NSEQ + i0 + r0) * DHEAD;
        const float* q1 = q0 + 8 * DHEAD;
        #pragma unroll
        for (int kk = 0; kk < 4; kk++) {
            float2 x0 = *(const float2*)(q0 + 16 * kk + 2 * tg);
            float2 x1 = *(const float2*)(q1 + 16 * kk + 2 * tg);
            float2 x2 = *(const float2*)(q0 + 16 * kk + 2 * tg + 8);
            float2 x3 = *(const float2*)(q1 + 16 * kk + 2 * tg + 8);
            qf[kk][0] = packh2(x0.x, x0.y);
            qf[kk][1] = packh2(x1.x, x1.y);
            qf[kk][2] = packh2(x2.x, x2.y);
            qf[kk][3] = packh2(x3.x, x3.y);
        }
    }

    float o[8][4];
    #pragma unroll
    for (int nt = 0; nt < 8; nt++)
        #pragma unroll
        for (int c = 0; c < 4; c++) o[nt][c] = 0.f;
    float m0 = NEG, m1 = NEG, l0 = 0.f, l1 = 0.f;

    const int lrA = (lane & 7) + ((lane >> 4) << 3);
    const int lcA = (lane >> 3) & 1;
    const int lrB = (lane & 7) + (((lane >> 3) & 1) << 3);
    const int lcB = (lane >> 4) & 1;
    const unsigned ksB = sh_base + SW_KS * 4;
    const unsigned vsB = sh_base + SW_VS * 4;

    for (int bn = 0; bn <= bm; bn++) {
        const int j0  = bn * BN;
        const int cur = bn & 1;

        __syncthreads();   // all warps done with buf[cur^1] (iter bn-1's tile)

        if (bn < bm) {
            // prefetch tile bn+1 into the buffer just freed
            const int   nxt = cur ^ 1;
            const char* kb  = khB + (size_t)(j0 + BN) * 128;
            const char* vb  = vhB + (size_t)(j0 + BN) * 128;
            const float* bt = bTil + (j0 + BN);
            #pragma unroll
            for (int t = 0; t < 4; t++) {
                int row = kvRow + t * 16;
                unsigned dsw = nxt * 8192 + row * 128 + (((kvCh ^ (row & 7)) << 4));
                cp16(sh_base + SW_KS * 4 + dsw, kb + row * 128 + kvCh * 16);
                cp16(sh_base + SW_VS * 4 + dsw, vb + row * 128 + kvCh * 16);
            }
            #pragma unroll
            for (int t = 0; t < 8; t++) {
                int row = bRow + t * 8;
                cp16(sh_base + (SW_BIAS + nxt * BIAS_BUF + row * BIAS_STRIDE + bCh * 4) * 4,
                     bt + (size_t)row * NSEQ + bCh * 4);
            }
            asm volatile("cp.async.commit_group;");
            asm volatile("cp.async.wait_group 1;");   // current tile's group done
        } else {
            asm volatile("cp.async.wait_group 0;");
        }
        __syncthreads();   // current buffers visible to all warps

        // ---- GEMM1: S = Q * K^T ----
        float s[8][4];
        #pragma unroll
        for (int nt = 0; nt < 8; nt++)
            #pragma unroll
            for (int c = 0; c < 4; c++) s[nt][c] = 0.f;

        #pragma unroll
        for (int kk = 0; kk < 4; kk++) {
            #pragma unroll
            for (int ntp = 0; ntp < 4; ntp++) {
                int row   = 16 * ntp + lrA;
                int chunk = 2 * kk + lcA;
                unsigned addr = ksB + cur * 8192 + row * 128 + ((chunk ^ (row & 7)) << 4);
                unsigned kb0, kb1, kb2, kb3;
                ldsm_x4(kb0, kb1, kb2, kb3, addr);
                mma_f16(s[2 * ntp],     qf[kk], kb0, kb1);
                mma_f16(s[2 * ntp + 1], qf[kk], kb2, kb3);
            }
        }

        // ---- epilogue: bias + masks + online softmax (P stays in regs) ----
        const bool diag = (bn == bm);
        const float* bb = sm + SW_BIAS + cur * BIAS_BUF;
        const float* Ms = sm + SW_MASK + j0;
        float vmax0 = NEG, vmax1 = NEG;
        #pragma unroll
        for (int nt = 0; nt < 8; nt++) {
            const int c0 = nt * 8 + 2 * tg;
            float2 bv0 = *(const float2*)(bb + r0 * BIAS_STRIDE + c0);
            float2 bv1 = *(const float2*)(bb + r1 * BIAS_STRIDE + c0);
            float2 mk  = *(const float2*)(Ms + c0);
            float x00 = fmaf(s[nt][0], scale, bv0.x) + mk.x;
            float x01 = fmaf(s[nt][1], scale, bv0.y) + mk.y;
            float x10 = fmaf(s[nt][2], scale, bv1.x) + mk.x;
            float x11 = fmaf(s[nt][3], scale, bv1.y) + mk.y;
            if (diag) {
                if (c0     > r0) x00 = NEG;
                if (c0 + 1 > r0) x01 = NEG;
                if (c0     > r1) x10 = NEG;
                if (c0 + 1 > r1) x11 = NEG;
            }
            s[nt][0] = x00; s[nt][1] = x01; s[nt][2] = x10; s[nt][3] = x11;
            vmax0 = fmaxf(vmax0, fmaxf(x00, x01));
            vmax1 = fmaxf(vmax1, fmaxf(x10, x11));
        }
        vmax0 = fmaxf(vmax0, __shfl_xor_sync(0xffffffffu, vmax0, 1));
        vmax0 = fmaxf(vmax0, __shfl_xor_sync(0xffffffffu, vmax0, 2));
        vmax1 = fmaxf(vmax1, __shfl_xor_sync(0xffffffffu, vmax1, 1));
        vmax1 = fmaxf(vmax1, __shfl_xor_sync(0xffffffffu, vmax1, 2));

        float mn0 = fmaxf(m0, vmax0), mn1 = fmaxf(m1, vmax1);
        float corr0 = __expf(m0 - mn0), corr1 = __expf(m1 - mn1);
        m0 = mn0; m1 = mn1;

        unsigned ph0[8], ph1[8];
        float sum0 = 0.f, sum1 = 0.f;
        #pragma unroll
        for (int nt = 0; nt < 8; nt++) {
            float p00 = __expf(s[nt][0] - m0);
            float p01 = __expf(s[nt][1] - m0);
            float p10 = __expf(s[nt][2] - m1);
            float p11 = __expf(s[nt][3] - m1);
            sum0 += p00 + p01;
            sum1 += p10 + p11;
            ph0[nt] = packh2(p00, p01);
            ph1[nt] = packh2(p10, p11);
        }
        sum0 += __shfl_xor_sync(0xffffffffu, sum0, 1);
        sum0 += __shfl_xor_sync(0xffffffffu, sum0, 2);
        sum1 += __shfl_xor_sync(0xffffffffu, sum1, 1);
        sum1 += __shfl_xor_sync(0xffffffffu, sum1, 2);
        l0 = l0 * corr0 + sum0;
        l1 = l1 * corr1 + sum1;
        #pragma unroll
        for (int nt = 0; nt < 8; nt++) {
            o[nt][0] *= corr0; o[nt][1] *= corr0;
            o[nt][2] *= corr1; o[nt][3] *= corr1;
        }

        // ---- GEMM2: O += P * V (A-frags from registers) ----
        #pragma unroll
        for (int kk = 0; kk < 4; kk++) {
            unsigned pa[4] = { ph0[2 * kk], ph1[2 * kk],
                               ph0[2 * kk + 1], ph1[2 * kk + 1] };
            #pragma unroll
            for (int ntp = 0; ntp < 4; ntp++) {
                int row   = 16 * kk + lrB;
                int chunk = 2 * ntp + lcB;
                unsigned addr = vsB + cur * 8192 + row * 128 + ((chunk ^ (row & 7)) << 4);
                unsigned v0, v1, v2, v3;
                ldsm_x4_t(v0, v1, v2, v3, addr);
                mma_f16(o[2 * ntp],     pa, v0, v1);
                mma_f16(o[2 * ntp + 1], pa, v2, v3);
            }
        }
    }

    // ---- finalize ----
    float inv0 = 1.f / l0, inv1 = 1.f / l1;
    float* ob = out + ((size_t)bh * NSEQ + i0) * DHEAD;
    #pragma unroll
    for (int nt = 0; nt < 8; nt++) {
        const int c0 = nt * 8 + 2 * tg;
        *(float2*)(ob + r0 * DHEAD + c0) =
            make_float2(o[nt][0] * inv0, o[nt][1] * inv0);
        *(float2*)(ob + r1 * DHEAD + c0) =
            make_float2(o[nt][2] * inv1, o[nt][3] * inv1);
    }
}

extern "C" void kernel_launch(void* const* d_in, const int* in_sizes, int n_in,
                              void* d_out, int out_size)
{
    const float*        q    = (const float*)d_in[0];
    const float*        k    = (const float*)d_in[1];
    const float*        v    = (const float*)d_in[2];
    const unsigned int* mask = (const unsigned int*)d_in[3];
    const float*        bias = (const float*)d_in[4];
    float*              out  = (float*)d_out;

    // pre-pass: K/V fp32 -> fp16 scratch (once per launch)
    convert_kv_kernel<<<BATCH * NSEQ * DHEAD / 2 / 256, 256>>>(k, v);

    cudaFuncSetAttribute(attend_kernel,
                         cudaFuncAttributeMaxDynamicSharedMemorySize,
                         SW_TOTAL * (int)sizeof(float));

    dim3 grid(NSEQ / BM, 4 * HEADS);   // 16 x 32
    attend_kernel<<<grid, NTHREADS, SW_TOTAL * sizeof(float)>>>(
        q, mask, bias, out);
}

// round 5
// speedup vs baseline: 5.0303x; 1.0490x over previous
#include <cuda_runtime.h>
#include <cuda_fp16.h>
#include <math_constants.h>

#define NSEQ 1024
#define DHEAD 64
#define HEADS 8
#define BATCH 4
#define BM 64
#define BN 64
#define NTHREADS 128

// shared memory word (4B) offsets
#define SW_KS 0                          // half [2][64][64], swizzled (2*2048 words)
#define SW_VS 4096                       // half [2][64][64], swizzled
#define SW_BIAS 8192                     // float [2][64][72]
#define BIAS_STRIDE 72
#define BIAS_BUF (64*BIAS_STRIDE)
#define SW_MASK (SW_BIAS + 2*BIAS_BUF)   // float [1024]
#define SW_TOTAL (SW_MASK + NSEQ)        // 18432 words = 73728 B

// K/V converted to fp16 once per launch (allocation-free scratch)
__device__ __half2 g_kh[BATCH * NSEQ * DHEAD / 2];
__device__ __half2 g_vh[BATCH * NSEQ * DHEAD / 2];

__device__ __forceinline__ unsigned packh2(float lo, float hi) {
    __half2 h = __floats2half2_rn(lo, hi);
    return *(unsigned*)&h;
}

__global__ __launch_bounds__(512)
void convert_kv_kernel(const float4* __restrict__ k4,
                       const float4* __restrict__ v4)
{
    int i = blockIdx.x * blockDim.x + threadIdx.x;   // over float4 groups
    float4 a = k4[i];
    ((uint2*)g_kh)[i] = make_uint2(packh2(a.x, a.y), packh2(a.z, a.w));
    float4 b = v4[i];
    ((uint2*)g_vh)[i] = make_uint2(packh2(b.x, b.y), packh2(b.z, b.w));
}

__device__ __forceinline__ void ldsm_x4(unsigned& r0, unsigned& r1,
                                        unsigned& r2, unsigned& r3, unsigned addr) {
    asm volatile("ldmatrix.sync.aligned.m8n8.x4.shared.b16 {%0,%1,%2,%3}, [%4];"
                 : "=r"(r0), "=r"(r1), "=r"(r2), "=r"(r3) : "r"(addr));
}
__device__ __forceinline__ void ldsm_x4_t(unsigned& r0, unsigned& r1,
                                          unsigned& r2, unsigned& r3, unsigned addr) {
    asm volatile("ldmatrix.sync.aligned.m8n8.x4.trans.shared.b16 {%0,%1,%2,%3}, [%4];"
                 : "=r"(r0), "=r"(r1), "=r"(r2), "=r"(r3) : "r"(addr));
}
__device__ __forceinline__ void mma_f16(float (&c)[4], const unsigned (&a)[4],
                                        unsigned b0, unsigned b1) {
    asm volatile(
        "mma.sync.aligned.m16n8k16.row.col.f32.f16.f16.f32 "
        "{%0,%1,%2,%3}, {%4,%5,%6,%7}, {%8,%9}, {%0,%1,%2,%3};"
        : "+f"(c[0]), "+f"(c[1]), "+f"(c[2]), "+f"(c[3])
        : "r"(a[0]), "r"(a[1]), "r"(a[2]), "r"(a[3]), "r"(b0), "r"(b1));
}
__device__ __forceinline__ void cp16(unsigned dst_sh, const void* src) {
    asm volatile("cp.async.cg.shared.global [%0], [%1], 16;" :: "r"(dst_sh), "l"(src));
}

__global__ __launch_bounds__(NTHREADS, 3)
void attend_kernel(const float* __restrict__ q,
                   const unsigned int* __restrict__ mask,
                   const float* __restrict__ bias,
                   float* __restrict__ out)
{
    extern __shared__ float sm[];
    const unsigned sh_base = (unsigned)__cvta_generic_to_shared(sm);

    const int tid  = threadIdx.x;
    const int lane = tid & 31;
    const int warp = tid >> 5;
    const int g    = lane >> 2;
    const int tg   = lane & 3;
    const int bm   = (gridDim.x - 1) - blockIdx.x;  // heavy tiles first
    const int bh   = blockIdx.y;                    // b*H + h
    const int b    = bh >> 3;
    const int i0   = bm * BM;
    const int r0   = warp * 16 + g;
    const int r1   = r0 + 8;

    const float NEG = -CUDART_INF_F;

    const char*  khB  = (const char*)g_kh + (size_t)b * NSEQ * DHEAD * 2;
    const char*  vhB  = (const char*)g_vh + (size_t)b * NSEQ * DHEAD * 2;
    const float* bTil = bias + ((size_t)bh * NSEQ + i0) * NSEQ;

    // loader decomposition
    const int kvRow = tid >> 3;        // K/V: 512 tasks, 4/thread (row step 16)
    const int kvCh  = tid & 7;
    const int bRow  = tid >> 4;        // bias: 1024 tasks, 8/thread (row step 8)
    const int bCh   = tid & 15;

    // ---- prologue: async-load tile 0 into buf 0 ----
    {
        #pragma unroll
        for (int t = 0; t < 4; t++) {
            int row = kvRow + t * 16;
            unsigned dsw = row * 128 + (((kvCh ^ (row & 7)) << 4));
            cp16(sh_base + SW_KS * 4 + dsw, khB + row * 128 + kvCh * 16);
            cp16(sh_base + SW_VS * 4 + dsw, vhB + row * 128 + kvCh * 16);
        }
        #pragma unroll
        for (int t = 0; t < 8; t++) {
            int row = bRow + t * 8;
            cp16(sh_base + (SW_BIAS + row * BIAS_STRIDE + bCh * 4) * 4,
                 bTil + (size_t)row * NSEQ + bCh * 4);
        }
        asm volatile("cp.async.commit_group;");
    }

    // ---- key-padding mask -> smem (whole row, once) ----
    {
        float* Ms = sm + SW_MASK;
        const unsigned int* mrow = mask + b * NSEQ;
        #pragma unroll
        for (int t = 0; t < 8; t++)
            Ms[tid + t * NTHREADS] = (mrow[tid + t * NTHREADS] != 0u) ? 0.f : NEG;
    }

    // ---- Q fragments with scale folded in (exact: 0.125 = 2^-3) ----
    unsigned qf[4][4];
    {
        const float sc = 0.125f;
        const float* q0 = q + ((size_t)bh * NSEQ + i0 + r0) * DHEAD;
        const float* q1 = q0 + 8 * DHEAD;
        #pragma unroll
        for (int kk = 0; kk < 4; kk++) {
            float2 x0 = *(const float2*)(q0 + 16 * kk + 2 * tg);
            float2 x1 = *(const float2*)(q1 + 16 * kk + 2 * tg);
            float2 x2 = *(const float2*)(q0 + 16 * kk + 2 * tg + 8);
            float2 x3 = *(const float2*)(q1 + 16 * kk + 2 * tg + 8);
            qf[kk][0] = packh2(x0.x * sc, x0.y * sc);
            qf[kk][1] = packh2(x1.x * sc, x1.y * sc);
            qf[kk][2] = packh2(x2.x * sc, x2.y * sc);
            qf[kk][3] = packh2(x3.x * sc, x3.y * sc);
        }
    }

    float o[8][4];
    #pragma unroll
    for (int nt = 0; nt < 8; nt++)
        #pragma unroll
        for (int c = 0; c < 4; c++) o[nt][c] = 0.f;
    float m0 = NEG, m1 = NEG, l0 = 0.f, l1 = 0.f;

    const int lrA = (lane & 7) + ((lane >> 4) << 3);
    const int lcA = (lane >> 3) & 1;
    const int lrB = (lane & 7) + (((lane >> 3) & 1) << 3);
    const int lcB = (lane >> 4) & 1;
    const unsigned ksB = sh_base + SW_KS * 4;
    const unsigned vsB = sh_base + SW_VS * 4;

    for (int bn = 0; bn <= bm; bn++) {
        const int j0  = bn * BN;
        const int cur = bn & 1;

        __syncthreads();   // all warps done with buf[cur^1] (iter bn-1's tile)

        if (bn < bm) {
            const int   nxt = cur ^ 1;
            const char* kb  = khB + (size_t)(j0 + BN) * 128;
            const char* vb  = vhB + (size_t)(j0 + BN) * 128;
            const float* bt = bTil + (j0 + BN);
            #pragma unroll
            for (int t = 0; t < 4; t++) {
                int row = kvRow + t * 16;
                unsigned dsw = nxt * 8192 + row * 128 + (((kvCh ^ (row & 7)) << 4));
                cp16(sh_base + SW_KS * 4 + dsw, kb + row * 128 + kvCh * 16);
                cp16(sh_base + SW_VS * 4 + dsw, vb + row * 128 + kvCh * 16);
            }
            #pragma unroll
            for (int t = 0; t < 8; t++) {
                int row = bRow + t * 8;
                cp16(sh_base + (SW_BIAS + nxt * BIAS_BUF + row * BIAS_STRIDE + bCh * 4) * 4,
                     bt + (size_t)row * NSEQ + bCh * 4);
            }
            asm volatile("cp.async.commit_group;");
            asm volatile("cp.async.wait_group 1;");
        } else {
            asm volatile("cp.async.wait_group 0;");
        }
        __syncthreads();   // current buffers visible to all warps

        // ---- init S accumulators = bias + mask (pre-GEMM, overlaps LDSM) ----
        float s[8][4];
        {
            const float* bb = sm + SW_BIAS + cur * BIAS_BUF;
            const float* Ms = sm + SW_MASK + j0;
            #pragma unroll
            for (int nt = 0; nt < 8; nt++) {
                const int c0 = nt * 8 + 2 * tg;
                float2 bv0 = *(const float2*)(bb + r0 * BIAS_STRIDE + c0);
                float2 bv1 = *(const float2*)(bb + r1 * BIAS_STRIDE + c0);
                float2 mk  = *(const float2*)(Ms + c0);
                s[nt][0] = bv0.x + mk.x;
                s[nt][1] = bv0.y + mk.y;
                s[nt][2] = bv1.x + mk.x;
                s[nt][3] = bv1.y + mk.y;
            }
        }

        // ---- GEMM1: S += (scale*Q) * K^T ----
        #pragma unroll
        for (int kk = 0; kk < 4; kk++) {
            #pragma unroll
            for (int ntp = 0; ntp < 4; ntp++) {
                int row   = 16 * ntp + lrA;
                int chunk = 2 * kk + lcA;
                unsigned addr = ksB + cur * 8192 + row * 128 + ((chunk ^ (row & 7)) << 4);
                unsigned kb0, kb1, kb2, kb3;
                ldsm_x4(kb0, kb1, kb2, kb3, addr);
                mma_f16(s[2 * ntp],     qf[kk], kb0, kb1);
                mma_f16(s[2 * ntp + 1], qf[kk], kb2, kb3);
            }
        }

        // ---- epilogue: causal (diag only) + online softmax ----
        if (bn == bm) {
            #pragma unroll
            for (int nt = 0; nt < 8; nt++) {
                const int c0 = nt * 8 + 2 * tg;
                if (c0     > r0) s[nt][0] = NEG;
                if (c0 + 1 > r0) s[nt][1] = NEG;
                if (c0     > r1) s[nt][2] = NEG;
                if (c0 + 1 > r1) s[nt][3] = NEG;
            }
        }
        float vmax0 = NEG, vmax1 = NEG;
        #pragma unroll
        for (int nt = 0; nt < 8; nt++) {
            vmax0 = fmaxf(vmax0, fmaxf(s[nt][0], s[nt][1]));
            vmax1 = fmaxf(vmax1, fmaxf(s[nt][2], s[nt][3]));
        }
        vmax0 = fmaxf(vmax0, __shfl_xor_sync(0xffffffffu, vmax0, 1));
        vmax0 = fmaxf(vmax0, __shfl_xor_sync(0xffffffffu, vmax0, 2));
        vmax1 = fmaxf(vmax1, __shfl_xor_sync(0xffffffffu, vmax1, 1));
        vmax1 = fmaxf(vmax1, __shfl_xor_sync(0xffffffffu, vmax1, 2));

        float mn0 = fmaxf(m0, vmax0), mn1 = fmaxf(m1, vmax1);
        float corr0 = __expf(m0 - mn0), corr1 = __expf(m1 - mn1);
        m0 = mn0; m1 = mn1;

        unsigned ph0[8], ph1[8];
        float sum0 = 0.f, sum1 = 0.f;
        #pragma unroll
        for (int nt = 0; nt < 8; nt++) {
            float p00 = __expf(s[nt][0] - m0);
            float p01 = __expf(s[nt][1] - m0);
            float p10 = __expf(s[nt][2] - m1);
            float p11 = __expf(s[nt][3] - m1);
            sum0 += p00 + p01;
            sum1 += p10 + p11;
            ph0[nt] = packh2(p00, p01);
            ph1[nt] = packh2(p10, p11);
        }
        sum0 += __shfl_xor_sync(0xffffffffu, sum0, 1);
        sum0 += __shfl_xor_sync(0xffffffffu, sum0, 2);
        sum1 += __shfl_xor_sync(0xffffffffu, sum1, 1);
        sum1 += __shfl_xor_sync(0xffffffffu, sum1, 2);
        l0 = l0 * corr0 + sum0;
        l1 = l1 * corr1 + sum1;
        #pragma unroll
        for (int nt = 0; nt < 8; nt++) {
            o[nt][0] *= corr0; o[nt][1] *= corr0;
            o[nt][2] *= corr1; o[nt][3] *= corr1;
        }

        // ---- GEMM2: O += P * V (A-frags from registers) ----
        #pragma unroll
        for (int kk = 0; kk < 4; kk++) {
            unsigned pa[4] = { ph0[2 * kk], ph1[2 * kk],
                               ph0[2 * kk + 1], ph1[2 * kk + 1] };
            #pragma unroll
            for (int ntp = 0; ntp < 4; ntp++) {
                int row   = 16 * kk + lrB;
                int chunk = 2 * ntp + lcB;
                unsigned addr = vsB + cur * 8192 + row * 128 + ((chunk ^ (row & 7)) << 4);
                unsigned v0, v1, v2, v3;
                ldsm_x4_t(v0, v1, v2, v3, addr);
                mma_f16(o[2 * ntp],     pa, v0, v1);
                mma_f16(o[2 * ntp + 1], pa, v2, v3);
            }
        }
    }

    // ---- finalize ----
    float inv0 = 1.f / l0, inv1 = 1.f / l1;
    float* ob = out + ((size_t)bh * NSEQ + i0) * DHEAD;
    #pragma unroll
    for (int nt = 0; nt < 8; nt++) {
        const int c0 = nt * 8 + 2 * tg;
        *(float2*)(ob + r0 * DHEAD + c0) =
            make_float2(o[nt][0] * inv0, o[nt][1] * inv0);
        *(float2*)(ob + r1 * DHEAD + c0) =
            make_float2(o[nt][2] * inv1, o[nt][3] * inv1);
    }
}

extern "C" void kernel_launch(void* const* d_in, const int* in_sizes, int n_in,
                              void* d_out, int out_size)
{
    const float*        q    = (const float*)d_in[0];
    const float*        k    = (const float*)d_in[1];
    const float*        v    = (const float*)d_in[2];
    const unsigned int* mask = (const unsigned int*)d_in[3];
    const float*        bias = (const float*)d_in[4];
    float*              out  = (float*)d_out;

    // pre-pass: K/V fp32 -> fp16 scratch (once per launch), float4-vectorized
    convert_kv_kernel<<<BATCH * NSEQ * DHEAD / 4 / 512, 512>>>(
        (const float4*)k, (const float4*)v);

    cudaFuncSetAttribute(attend_kernel,
                         cudaFuncAttributeMaxDynamicSharedMemorySize,
                         SW_TOTAL * (int)sizeof(float));

    dim3 grid(NSEQ / BM, 4 * HEADS);   // 16 x 32
    attend_kernel<<<grid, NTHREADS, SW_TOTAL * sizeof(float)>>>(
        q, mask, bias, out);
}